// round 14
// baseline (speedup 1.0000x reference)
#include <cuda_runtime.h>
#include <cuda_fp16.h>
#include <cstdint>

#define H     1024
#define V     32000
#define DEPTH 10
#define KDIM  1024

// ---------------- scratch (no runtime allocation allowed) ----------------
__device__ float g_h0[1024 * H];            // ping
__device__ float g_h1[1024 * H];            // pong
__device__ float g_gh[512 * 6 * H];         // gate pre-activations

// ---------------- mma primitives ------------------------------------------
__device__ __forceinline__ float cvt_tf32(float x) {
    uint32_t b;
    asm("cvt.rna.tf32.f32 %0, %1;" : "=r"(b) : "f"(x));
    return __uint_as_float(b);
}

__device__ __forceinline__ void mma_16x8x8(float c[4], const uint32_t a[4], const uint32_t b[2]) {
    asm volatile(
        "mma.sync.aligned.m16n8k8.row.col.f32.tf32.tf32.f32 "
        "{%0,%1,%2,%3}, {%4,%5,%6,%7}, {%8,%9}, {%0,%1,%2,%3};\n"
        : "+f"(c[0]), "+f"(c[1]), "+f"(c[2]), "+f"(c[3])
        : "r"(a[0]), "r"(a[1]), "r"(a[2]), "r"(a[3]), "r"(b[0]), "r"(b[1]));
}

__device__ __forceinline__ void mma_f16m(float c[4], const uint32_t a[4], const uint32_t b[2]) {
    asm volatile(
        "mma.sync.aligned.m16n8k16.row.col.f32.f16.f16.f32 "
        "{%0,%1,%2,%3}, {%4,%5,%6,%7}, {%8,%9}, {%0,%1,%2,%3};\n"
        : "+f"(c[0]), "+f"(c[1]), "+f"(c[2]), "+f"(c[3])
        : "r"(a[0]), "r"(a[1]), "r"(a[2]), "r"(a[3]), "r"(b[0]), "r"(b[1]));
}

#define BK 32
#define PAD 4

// ================= tf32 GEMM, BM=32 tile (tree levels M>=128) =============
// 256 threads = 8 warps (2 x 4); CTA tile 32 x 128; warp tile 16 x 32.
__global__ void __launch_bounds__(256, 1)
gemm_tf32_m32(const float* __restrict__ A, int M,
              const float* __restrict__ B0, const float* __restrict__ B1, int nsplit,
              const float* __restrict__ bias0, const float* __restrict__ bias1,
              float* __restrict__ C, int Ntot)
{
    __shared__ float sA[32][BK + PAD];
    __shared__ float sB[128][BK + PAD];

    const int tid  = threadIdx.x;
    const int lane = tid & 31;
    const int warp = tid >> 5;
    const int wm = (warp >> 2) * 16;     // 0 or 16
    const int wn = (warp & 3) * 32;
    const int bm = blockIdx.y * 32;      // M multiple of 32 -> no row guards
    const int bn = blockIdx.x * 128;

    const int lr = tid >> 3;             // 0..31
    const int lc = (tid & 7) * 4;

    float acc[4][4];
    #pragma unroll
    for (int j = 0; j < 4; j++)
        #pragma unroll
        for (int k = 0; k < 4; k++) acc[j][k] = 0.f;

    const float* Arow = A + (size_t)(bm + lr) * KDIM;
    const float* Brow[4];
    #pragma unroll
    for (int i = 0; i < 4; i++) {
        int n = bn + lr + 32 * i;
        Brow[i] = (n < nsplit) ? (B0 + (size_t)n * KDIM)
                               : (B1 + (size_t)(n - nsplit) * KDIM);
    }

    float4 pa = *(const float4*)(Arow + lc);
    float4 pb[4];
    #pragma unroll
    for (int i = 0; i < 4; i++) pb[i] = *(const float4*)(Brow[i] + lc);

    const int NK = KDIM / BK;
    for (int kt = 0; kt < NK; kt++) {
        {
            float4 va = pa;
            va.x = cvt_tf32(va.x); va.y = cvt_tf32(va.y);
            va.z = cvt_tf32(va.z); va.w = cvt_tf32(va.w);
            *(float4*)&sA[lr][lc] = va;
        }
        #pragma unroll
        for (int i = 0; i < 4; i++) {
            float4 vb = pb[i];
            vb.x = cvt_tf32(vb.x); vb.y = cvt_tf32(vb.y);
            vb.z = cvt_tf32(vb.z); vb.w = cvt_tf32(vb.w);
            *(float4*)&sB[lr + 32 * i][lc] = vb;
        }
        __syncthreads();

        if (kt + 1 < NK) {
            const int k0 = (kt + 1) * BK;
            pa = *(const float4*)(Arow + k0 + lc);
            #pragma unroll
            for (int i = 0; i < 4; i++) pb[i] = *(const float4*)(Brow[i] + k0 + lc);
        }

        #pragma unroll
        for (int kk = 0; kk < 4; kk++) {
            const int k = kk * 8;
            uint32_t af[4];
            {
                int r0 = wm + (lane >> 2);
                int c0 = k + (lane & 3);
                af[0] = __float_as_uint(sA[r0][c0]);
                af[1] = __float_as_uint(sA[r0 + 8][c0]);
                af[2] = __float_as_uint(sA[r0][c0 + 4]);
                af[3] = __float_as_uint(sA[r0 + 8][c0 + 4]);
            }
            uint32_t bf[4][2];
            #pragma unroll
            for (int nf = 0; nf < 4; nf++) {
                int n0 = wn + nf * 8 + (lane >> 2);
                int kr = k + (lane & 3);
                bf[nf][0] = __float_as_uint(sB[n0][kr]);
                bf[nf][1] = __float_as_uint(sB[n0][kr + 4]);
            }
            #pragma unroll
            for (int nf = 0; nf < 4; nf++)
                mma_16x8x8(acc[nf], af, bf[nf]);
        }
        __syncthreads();
    }

    #pragma unroll
    for (int nf = 0; nf < 4; nf++) {
        int c0 = bn + wn + nf * 8 + (lane & 3) * 2;
        const float* bp = (c0 < nsplit) ? bias0 : bias1;
        int cb = (c0 < nsplit) ? c0 : c0 - nsplit;
        float bv0 = bp[cb], bv1 = bp[cb + 1];
        int r0 = bm + wm + (lane >> 2);
        C[(size_t)r0 * Ntot + c0]           = acc[nf][0] + bv0;
        C[(size_t)r0 * Ntot + c0 + 1]       = acc[nf][1] + bv1;
        C[(size_t)(r0 + 8) * Ntot + c0]     = acc[nf][2] + bv0;
        C[(size_t)(r0 + 8) * Ntot + c0 + 1] = acc[nf][3] + bv1;
    }
}

// ================= tf32 GEMM, BM=16 tile (tree levels M=4..64) ============
// 128 threads = 4 warps; CTA tile 16 x 128; warp tile 16 x 32.
__global__ void __launch_bounds__(128, 1)
gemm_tf32_m16(const float* __restrict__ A, int M,
              const float* __restrict__ B0, const float* __restrict__ B1, int nsplit,
              const float* __restrict__ bias0, const float* __restrict__ bias1,
              float* __restrict__ C, int Ntot)
{
    __shared__ float sA[16][BK + PAD];
    __shared__ float sB[128][BK + PAD];

    const int tid  = threadIdx.x;
    const int lane = tid & 31;
    const int warp = tid >> 5;          // 0..3
    const int wn   = warp * 32;
    const int bm = blockIdx.y * 16;
    const int bn = blockIdx.x * 128;

    const int lr = tid >> 3;            // 0..15
    const int lc = (tid & 7) * 4;       // 0..28

    float acc[4][4];
    #pragma unroll
    for (int j = 0; j < 4; j++)
        #pragma unroll
        for (int k = 0; k < 4; k++) acc[j][k] = 0.f;

    const int am = bm + lr;
    const bool aok = (am < M);
    const float* Arow = A + (size_t)(aok ? am : 0) * KDIM;

    const float* Brow[8];
    #pragma unroll
    for (int i = 0; i < 8; i++) {
        int n = bn + lr + 16 * i;
        Brow[i] = (n < nsplit) ? (B0 + (size_t)n * KDIM)
                               : (B1 + (size_t)(n - nsplit) * KDIM);
    }

    float4 pa;
    float4 pb[8];
    pa = aok ? *(const float4*)(Arow + lc) : make_float4(0.f, 0.f, 0.f, 0.f);
    #pragma unroll
    for (int i = 0; i < 8; i++) pb[i] = *(const float4*)(Brow[i] + lc);

    const int NK = KDIM / BK;
    for (int kt = 0; kt < NK; kt++) {
        {
            float4 va = pa;
            va.x = cvt_tf32(va.x); va.y = cvt_tf32(va.y);
            va.z = cvt_tf32(va.z); va.w = cvt_tf32(va.w);
            *(float4*)&sA[lr][lc] = va;
        }
        #pragma unroll
        for (int i = 0; i < 8; i++) {
            float4 vb = pb[i];
            vb.x = cvt_tf32(vb.x); vb.y = cvt_tf32(vb.y);
            vb.z = cvt_tf32(vb.z); vb.w = cvt_tf32(vb.w);
            *(float4*)&sB[lr + 16 * i][lc] = vb;
        }
        __syncthreads();

        if (kt + 1 < NK) {
            const int k0 = (kt + 1) * BK;
            pa = aok ? *(const float4*)(Arow + k0 + lc) : make_float4(0.f, 0.f, 0.f, 0.f);
            #pragma unroll
            for (int i = 0; i < 8; i++) pb[i] = *(const float4*)(Brow[i] + k0 + lc);
        }

        #pragma unroll
        for (int kk = 0; kk < 4; kk++) {
            const int k = kk * 8;
            uint32_t af[4];
            {
                int r0 = lane >> 2;
                int c0 = k + (lane & 3);
                af[0] = __float_as_uint(sA[r0][c0]);
                af[1] = __float_as_uint(sA[r0 + 8][c0]);
                af[2] = __float_as_uint(sA[r0][c0 + 4]);
                af[3] = __float_as_uint(sA[r0 + 8][c0 + 4]);
            }
            uint32_t bf[4][2];
            #pragma unroll
            for (int nf = 0; nf < 4; nf++) {
                int n0 = wn + nf * 8 + (lane >> 2);
                int kr = k + (lane & 3);
                bf[nf][0] = __float_as_uint(sB[n0][kr]);
                bf[nf][1] = __float_as_uint(sB[n0][kr + 4]);
            }
            #pragma unroll
            for (int nf = 0; nf < 4; nf++)
                mma_16x8x8(acc[nf], af, bf[nf]);
        }
        __syncthreads();
    }

    #pragma unroll
    for (int nf = 0; nf < 4; nf++) {
        int c0 = bn + wn + nf * 8 + (lane & 3) * 2;
        const float* bp = (c0 < nsplit) ? bias0 : bias1;
        int cb = (c0 < nsplit) ? c0 : c0 - nsplit;
        float bv0 = bp[cb], bv1 = bp[cb + 1];
        int r0 = bm + (lane >> 2);
        if (r0 < M) {
            C[(size_t)r0 * Ntot + c0]     = acc[nf][0] + bv0;
            C[(size_t)r0 * Ntot + c0 + 1] = acc[nf][1] + bv1;
        }
        if (r0 + 8 < M) {
            C[(size_t)(r0 + 8) * Ntot + c0]     = acc[nf][2] + bv0;
            C[(size_t)(r0 + 8) * Ntot + c0 + 1] = acc[nf][3] + bv1;
        }
    }
}

// ================= small-M tree GEMM (M <= 2) =============================
__global__ void __launch_bounds__(256)
smallM_gemm(const float* __restrict__ hrow,
            const float* __restrict__ Wl, const float* __restrict__ Wr,
            const float* __restrict__ bl, const float* __restrict__ br,
            float* __restrict__ gh, int M)
{
    const int w    = (blockIdx.x * blockDim.x + threadIdx.x) >> 5;   // 0..6143
    const int lane = threadIdx.x & 31;

    const float* Wrow;
    float bias;
    if (w < 3 * H) { Wrow = Wl + (size_t)w * KDIM;           bias = bl[w]; }
    else           { Wrow = Wr + (size_t)(w - 3 * H) * KDIM; bias = br[w - 3 * H]; }

    float4 wr[8];
    #pragma unroll
    for (int i = 0; i < 8; i++) wr[i] = ((const float4*)Wrow)[lane + 32 * i];

    for (int m = 0; m < M; m++) {
        const float4* h4 = (const float4*)(hrow + (size_t)m * KDIM);
        float s = 0.f;
        #pragma unroll
        for (int i = 0; i < 8; i++) {
            float4 hv = h4[lane + 32 * i];
            s += wr[i].x * hv.x + wr[i].y * hv.y + wr[i].z * hv.z + wr[i].w * hv.w;
        }
        #pragma unroll
        for (int o = 16; o; o >>= 1) s += __shfl_xor_sync(0xffffffffu, s, o);
        if (lane == 0) gh[(size_t)m * (6 * H) + w] = s + bias;
    }
}

// ================= fp16 GEMM (final logits), fp32 in / convert at STS =====
// C[1024, V] = A[1024,1024] @ B^T + bias.  A,B fp32; fp16 conversion at smem
// store.  BM=BN=128, BK=32, 8 warps (2x4), warp tile 64x32, reg double-buffer.
#define HS 40     // halves per smem row (32 + 8 pad) -> 80B rows, conflict-free

__global__ void __launch_bounds__(256, 1)
gemm_f16v2(const float* __restrict__ A, const float* __restrict__ B,
           const float* __restrict__ bias, float* __restrict__ C, int Ntot)
{
    __shared__ __half sA[128][HS];
    __shared__ __half sB[128][HS];

    const int tid  = threadIdx.x;
    const int lane = tid & 31;
    const int warp = tid >> 5;
    const int wm = (warp >> 2) * 64;
    const int wn = (warp & 3) * 32;
    const int bm = blockIdx.y * 128;
    const int bn = blockIdx.x * 128;

    const int lr = tid >> 3;             // 0..31
    const int lc = (tid & 7) * 4;        // 0..28

    float acc[4][4][4];
    #pragma unroll
    for (int i = 0; i < 4; i++)
        #pragma unroll
        for (int j = 0; j < 4; j++)
            #pragma unroll
            for (int k = 0; k < 4; k++) acc[i][j][k] = 0.f;

    const float* Arow[4];
    const float* Brow[4];
    #pragma unroll
    for (int i = 0; i < 4; i++) {
        Arow[i] = A + (size_t)(bm + lr + 32 * i) * KDIM;
        Brow[i] = B + (size_t)(bn + lr + 32 * i) * KDIM;
    }

    float4 pa[4], pb[4];
    #pragma unroll
    for (int i = 0; i < 4; i++) {
        pa[i] = *(const float4*)(Arow[i] + lc);
        pb[i] = *(const float4*)(Brow[i] + lc);
    }

    const int NK = KDIM / BK;            // 32
    for (int kt = 0; kt < NK; kt++) {
        #pragma unroll
        for (int i = 0; i < 4; i++) {
            __half2 a01 = __floats2half2_rn(pa[i].x, pa[i].y);
            __half2 a23 = __floats2half2_rn(pa[i].z, pa[i].w);
            *(uint2*)&sA[lr + 32 * i][lc] =
                make_uint2(*(uint32_t*)&a01, *(uint32_t*)&a23);
            __half2 b01 = __floats2half2_rn(pb[i].x, pb[i].y);
            __half2 b23 = __floats2half2_rn(pb[i].z, pb[i].w);
            *(uint2*)&sB[lr + 32 * i][lc] =
                make_uint2(*(uint32_t*)&b01, *(uint32_t*)&b23);
        }
        __syncthreads();

        if (kt + 1 < NK) {
            const int k0 = (kt + 1) * BK;
            #pragma unroll
            for (int i = 0; i < 4; i++) {
                pa[i] = *(const float4*)(Arow[i] + k0 + lc);
                pb[i] = *(const float4*)(Brow[i] + k0 + lc);
            }
        }

        #pragma unroll
        for (int kc = 0; kc < 2; kc++) {
            const int k0 = kc * 16;
            uint32_t af[4][4], bf[4][2];
            #pragma unroll
            for (int mf = 0; mf < 4; mf++) {
                const __half* p = &sA[wm + mf * 16 + (lane >> 2)][k0 + (lane & 3) * 2];
                af[mf][0] = *(const uint32_t*)p;
                af[mf][1] = *(const uint32_t*)(p + 8 * HS);
                af[mf][2] = *(const uint32_t*)(p + 8);
                af[mf][3] = *(const uint32_t*)(p + 8 * HS + 8);
            }
            #pragma unroll
            for (int nf = 0; nf < 4; nf++) {
                const __half* p = &sB[wn + nf * 8 + (lane >> 2)][k0 + (lane & 3) * 2];
                bf[nf][0] = *(const uint32_t*)p;
                bf[nf][1] = *(const uint32_t*)(p + 8);
            }
            #pragma unroll
            for (int mf = 0; mf < 4; mf++)
                #pragma unroll
                for (int nf = 0; nf < 4; nf++)
                    mma_f16m(acc[mf][nf], af[mf], bf[nf]);
        }
        __syncthreads();
    }

    // epilogue (+bias); M = 1024, all rows valid
    #pragma unroll
    for (int nf = 0; nf < 4; nf++) {
        int c0 = bn + wn + nf * 8 + (lane & 3) * 2;
        float bv0 = __ldg(bias + c0), bv1 = __ldg(bias + c0 + 1);
        #pragma unroll
        for (int mf = 0; mf < 4; mf++) {
            int r0 = bm + wm + mf * 16 + (lane >> 2);
            C[(size_t)r0 * Ntot + c0]           = acc[mf][nf][0] + bv0;
            C[(size_t)r0 * Ntot + c0 + 1]       = acc[mf][nf][1] + bv1;
            C[(size_t)(r0 + 8) * Ntot + c0]     = acc[mf][nf][2] + bv0;
            C[(size_t)(r0 + 8) * Ntot + c0 + 1] = acc[mf][nf][3] + bv1;
        }
    }
}

// ================= GRU gate fusion + interleave ===========================
__device__ __forceinline__ float sigmoidf_(float x) { return 1.f / (1.f + expf(-x)); }

__global__ void gru_gates(const float* __restrict__ hcur,
                          const float* __restrict__ bih_l,
                          const float* __restrict__ bih_r,
                          float* __restrict__ hnext, int M)
{
    int idx = blockIdx.x * blockDim.x + threadIdx.x;
    if (idx >= M * H) return;
    int n = idx >> 10;
    int j = idx & (H - 1);
    float h = hcur[idx];
    const float* gh = g_gh + (size_t)n * (6 * H);   // bhh already added by GEMM

    {   // left child -> row 2n
        float r  = sigmoidf_(bih_l[j]         + gh[j]);
        float z  = sigmoidf_(bih_l[H + j]     + gh[H + j]);
        float nn = tanhf   (bih_l[2 * H + j]  + r * gh[2 * H + j]);
        hnext[(size_t)(2 * n) * H + j] = (1.f - z) * nn + z * h;
    }
    {   // right child -> row 2n+1
        const float* ghr = gh + 3 * H;
        float r  = sigmoidf_(bih_r[j]         + ghr[j]);
        float z  = sigmoidf_(bih_r[H + j]     + ghr[H + j]);
        float nn = tanhf   (bih_r[2 * H + j]  + r * ghr[2 * H + j]);
        hnext[(size_t)(2 * n + 1) * H + j] = (1.f - z) * nn + z * h;
    }
}

// ================= row-wise log_softmax (smem-resident row, 512 thr) ======
__global__ void __launch_bounds__(512) log_softmax_rows(float* __restrict__ out)
{
    extern __shared__ float sx[];                  // V floats (128000 B)
    const int row = blockIdx.x;
    float* x = out + (size_t)row * V;
    float4* x4 = (float4*)x;
    float4* s4 = (float4*)sx;
    const int V4 = V / 4;                          // 8000
    __shared__ float redm[16];
    __shared__ float reds[16];
    const int tid = threadIdx.x, lane = tid & 31, warp = tid >> 5;

    float m = -1e30f;
    for (int i = tid; i < V4; i += 512) {
        float4 v = x4[i];
        s4[i] = v;
        m = fmaxf(m, fmaxf(fmaxf(v.x, v.y), fmaxf(v.z, v.w)));
    }
    #pragma unroll
    for (int o = 16; o; o >>= 1) m = fmaxf(m, __shfl_xor_sync(0xffffffffu, m, o));
    if (lane == 0) redm[warp] = m;
    __syncthreads();
    if (warp == 0) {
        m = (lane < 16) ? redm[lane] : -1e30f;
        #pragma unroll
        for (int o = 8; o; o >>= 1) m = fmaxf(m, __shfl_xor_sync(0xffffffffu, m, o));
        if (lane == 0) redm[0] = m;
    }
    __syncthreads();
    m = redm[0];

    float s = 0.f;
    for (int i = tid; i < V4; i += 512) {
        float4 v = s4[i];
        s += expf(v.x - m) + expf(v.y - m) + expf(v.z - m) + expf(v.w - m);
    }
    #pragma unroll
    for (int o = 16; o; o >>= 1) s += __shfl_xor_sync(0xffffffffu, s, o);
    if (lane == 0) reds[warp] = s;
    __syncthreads();
    if (warp == 0) {
        s = (lane < 16) ? reds[lane] : 0.f;
        #pragma unroll
        for (int o = 8; o; o >>= 1) s += __shfl_xor_sync(0xffffffffu, s, o);
        if (lane == 0) reds[0] = s;
    }
    __syncthreads();
    const float lse = m + logf(reds[0]);

    for (int i = tid; i < V4; i += 512) {
        float4 v = s4[i];
        v.x -= lse; v.y -= lse; v.z -= lse; v.w -= lse;
        x4[i] = v;
    }
}

// ================= launch =================================================
extern "C" void kernel_launch(void* const* d_in, const int* in_sizes, int n_in,
                              void* d_out, int out_size)
{
    const float* hidden = (const float*)d_in[0];
    const float* Whh_l  = (const float*)d_in[1];
    const float* bih_l  = (const float*)d_in[2];
    const float* bhh_l  = (const float*)d_in[3];
    const float* Whh_r  = (const float*)d_in[4];
    const float* bih_r  = (const float*)d_in[5];
    const float* bhh_r  = (const float*)d_in[6];
    const float* Wout   = (const float*)d_in[7];
    const float* bout   = (const float*)d_in[8];
    float* out = (float*)d_out;

    float *h0, *h1, *gh;
    cudaGetSymbolAddress((void**)&h0, g_h0);
    cudaGetSymbolAddress((void**)&h1, g_h1);
    cudaGetSymbolAddress((void**)&gh, g_gh);

    cudaFuncSetAttribute(log_softmax_rows, cudaFuncAttributeMaxDynamicSharedMemorySize,
                         V * (int)sizeof(float));

    cudaMemcpyAsync(h0, hidden, H * sizeof(float), cudaMemcpyDeviceToDevice);

    float* cur = h0;
    float* nxt = h1;
    for (int d = 0; d < DEPTH; d++) {
        const int M = 1 << d;
        if (M <= 2) {
            smallM_gemm<<<6 * H / 8, 256>>>(cur, Whh_l, Whh_r, bhh_l, bhh_r, gh, M);
        } else if (M <= 64) {
            dim3 grid(6 * H / 128, (M + 15) / 16);
            gemm_tf32_m16<<<grid, 128>>>(cur, M, Whh_l, Whh_r, 3 * H,
                                         bhh_l, bhh_r, gh, 6 * H);
        } else {
            dim3 grid(6 * H / 128, M / 32);
            gemm_tf32_m32<<<grid, 256>>>(cur, M, Whh_l, Whh_r, 3 * H,
                                         bhh_l, bhh_r, gh, 6 * H);
        }
        gru_gates<<<(M * H + 255) / 256, 256>>>(cur, bih_l, bih_r, nxt, M);
        float* t = cur; cur = nxt; nxt = t;
    }

    // final: logits = h @ Wout^T + bout (fp32 in, fp16 mma, into d_out)
    dim3 gridf(V / 128, 1024 / 128);                 // (250, 8)
    gemm_f16v2<<<gridf, 256>>>(cur, Wout, bout, out, V);

    log_softmax_rows<<<1024, 512, V * sizeof(float)>>>(out);
}

// round 15
// speedup vs baseline: 1.3644x; 1.3644x over previous
#include <cuda_runtime.h>
#include <cuda_fp16.h>
#include <cstdint>

#define H     1024
#define V     32000
#define DEPTH 10
#define KDIM  1024

// ---------------- scratch (no runtime allocation allowed) ----------------
__device__ float  g_h0[1024 * H];            // ping
__device__ float  g_h1[1024 * H];            // pong
__device__ float  g_gh[512 * 6 * H];         // gate pre-activations
__device__ __half g_ahalf[1024 * H];         // h in fp16 (final GEMM A)
__device__ __half g_whalf[(size_t)V * H];    // Wout in fp16 (final GEMM B)

// ---------------- common helpers -----------------------------------------
__device__ __forceinline__ uint32_t smem_u32(const void* p) {
    uint32_t a;
    asm("{ .reg .u64 t; cvta.to.shared.u64 t, %1; cvt.u32.u64 %0, t; }"
        : "=r"(a) : "l"(p));
    return a;
}
__device__ __forceinline__ void cp16(uint32_t dst, const void* src) {
    asm volatile("cp.async.cg.shared.global [%0], [%1], 16;" :: "r"(dst), "l"(src));
}

// ================= fp32 -> fp16 conversion ================================
__global__ void conv_f16(const float* __restrict__ src, __half* __restrict__ dst, int n4)
{
    int i = blockIdx.x * blockDim.x + threadIdx.x;
    if (i >= n4) return;
    float4 v = ((const float4*)src)[i];
    __half2 a = __floats2half2_rn(v.x, v.y);
    __half2 b = __floats2half2_rn(v.z, v.w);
    uint2 p;
    p.x = *(uint32_t*)&a;
    p.y = *(uint32_t*)&b;
    ((uint2*)dst)[i] = p;
}

// ================= tf32 mma primitives ====================================
__device__ __forceinline__ float cvt_tf32(float x) {
    uint32_t b;
    asm("cvt.rna.tf32.f32 %0, %1;" : "=r"(b) : "f"(x));
    return __uint_as_float(b);
}

__device__ __forceinline__ void mma_16x8x8(float c[4], const uint32_t a[4], const uint32_t b[2]) {
    asm volatile(
        "mma.sync.aligned.m16n8k8.row.col.f32.tf32.tf32.f32 "
        "{%0,%1,%2,%3}, {%4,%5,%6,%7}, {%8,%9}, {%0,%1,%2,%3};\n"
        : "+f"(c[0]), "+f"(c[1]), "+f"(c[2]), "+f"(c[3])
        : "r"(a[0]), "r"(a[1]), "r"(a[2]), "r"(a[3]), "r"(b[0]), "r"(b[1]));
}

// ================= tf32 GEMM, BM=128 tile (tree levels M>=128) ============
#define BM 128
#define BN 128
#define BK 32
#define PAD 4

__global__ void __launch_bounds__(256, 1)
gemm_tf32(const float* __restrict__ A, int M,
          const float* __restrict__ B0, const float* __restrict__ B1, int nsplit,
          const float* __restrict__ bias0, const float* __restrict__ bias1,
          float* __restrict__ C, int Ntot)
{
    __shared__ float sA[BM][BK + PAD];
    __shared__ float sB[BN][BK + PAD];

    const int tid  = threadIdx.x;
    const int lane = tid & 31;
    const int warp = tid >> 5;
    const int wm = (warp >> 2) * 64;
    const int wn = (warp & 3) * 32;
    const int bm = blockIdx.y * BM;
    const int bn = blockIdx.x * BN;

    const int lr = tid >> 3;
    const int lc = (tid & 7) * 4;

    float acc[4][4][4];
    #pragma unroll
    for (int i = 0; i < 4; i++)
        #pragma unroll
        for (int j = 0; j < 4; j++)
            #pragma unroll
            for (int k = 0; k < 4; k++) acc[i][j][k] = 0.f;

    const float* Arow[4];
    const float* Brow[4];
    bool aval[4];
    #pragma unroll
    for (int i = 0; i < 4; i++) {
        int m = bm + lr + 32 * i;
        aval[i] = (m < M);
        Arow[i] = A + (size_t)(aval[i] ? m : 0) * KDIM;
        int n = bn + lr + 32 * i;
        Brow[i] = (n < nsplit) ? (B0 + (size_t)n * KDIM)
                               : (B1 + (size_t)(n - nsplit) * KDIM);
    }

    float4 pa[4], pb[4];
    #pragma unroll
    for (int i = 0; i < 4; i++) {
        pa[i] = aval[i] ? *(const float4*)(Arow[i] + lc) : make_float4(0.f, 0.f, 0.f, 0.f);
        pb[i] = *(const float4*)(Brow[i] + lc);
    }

    const int NK = KDIM / BK;
    for (int kt = 0; kt < NK; kt++) {
        #pragma unroll
        for (int i = 0; i < 4; i++) {
            float4 va = pa[i];
            va.x = cvt_tf32(va.x); va.y = cvt_tf32(va.y);
            va.z = cvt_tf32(va.z); va.w = cvt_tf32(va.w);
            *(float4*)&sA[lr + 32 * i][lc] = va;
            float4 vb = pb[i];
            vb.x = cvt_tf32(vb.x); vb.y = cvt_tf32(vb.y);
            vb.z = cvt_tf32(vb.z); vb.w = cvt_tf32(vb.w);
            *(float4*)&sB[lr + 32 * i][lc] = vb;
        }
        __syncthreads();

        if (kt + 1 < NK) {
            const int k0 = (kt + 1) * BK;
            #pragma unroll
            for (int i = 0; i < 4; i++) {
                pa[i] = aval[i] ? *(const float4*)(Arow[i] + k0 + lc)
                                : make_float4(0.f, 0.f, 0.f, 0.f);
                pb[i] = *(const float4*)(Brow[i] + k0 + lc);
            }
        }

        #pragma unroll
        for (int kk = 0; kk < 4; kk++) {
            const int k = kk * 8;
            uint32_t af[4][4];
            #pragma unroll
            for (int mf = 0; mf < 4; mf++) {
                int r0 = wm + mf * 16 + (lane >> 2);
                int c0 = k + (lane & 3);
                af[mf][0] = __float_as_uint(sA[r0][c0]);
                af[mf][1] = __float_as_uint(sA[r0 + 8][c0]);
                af[mf][2] = __float_as_uint(sA[r0][c0 + 4]);
                af[mf][3] = __float_as_uint(sA[r0 + 8][c0 + 4]);
            }
            uint32_t bf[4][2];
            #pragma unroll
            for (int nf = 0; nf < 4; nf++) {
                int n0 = wn + nf * 8 + (lane >> 2);
                int kr = k + (lane & 3);
                bf[nf][0] = __float_as_uint(sB[n0][kr]);
                bf[nf][1] = __float_as_uint(sB[n0][kr + 4]);
            }
            #pragma unroll
            for (int mf = 0; mf < 4; mf++)
                #pragma unroll
                for (int nf = 0; nf < 4; nf++)
                    mma_16x8x8(acc[mf][nf], af[mf], bf[nf]);
        }
        __syncthreads();
    }

    #pragma unroll
    for (int nf = 0; nf < 4; nf++) {
        int c0 = bn + wn + nf * 8 + (lane & 3) * 2;
        const float* bp = (c0 < nsplit) ? bias0 : bias1;
        int cb = (c0 < nsplit) ? c0 : c0 - nsplit;
        float bv0 = bp[cb], bv1 = bp[cb + 1];
        #pragma unroll
        for (int mf = 0; mf < 4; mf++) {
            int r0 = bm + wm + mf * 16 + (lane >> 2);
            if (r0 < M) {
                C[(size_t)r0 * Ntot + c0]     = acc[mf][nf][0] + bv0;
                C[(size_t)r0 * Ntot + c0 + 1] = acc[mf][nf][1] + bv1;
            }
            if (r0 + 8 < M) {
                C[(size_t)(r0 + 8) * Ntot + c0]     = acc[mf][nf][2] + bv0;
                C[(size_t)(r0 + 8) * Ntot + c0 + 1] = acc[mf][nf][3] + bv1;
            }
        }
    }
}

// ================= tf32 GEMM, BM=16 tile (tree levels M=4..64) ============
// 128 threads = 4 warps; CTA tile 16 x 128; warp tile 16 x 32.
__global__ void __launch_bounds__(128, 1)
gemm_tf32_m16(const float* __restrict__ A, int M,
              const float* __restrict__ B0, const float* __restrict__ B1, int nsplit,
              const float* __restrict__ bias0, const float* __restrict__ bias1,
              float* __restrict__ C, int Ntot)
{
    __shared__ float sA[16][BK + PAD];
    __shared__ float sB[128][BK + PAD];

    const int tid  = threadIdx.x;
    const int lane = tid & 31;
    const int warp = tid >> 5;          // 0..3
    const int wn   = warp * 32;
    const int bm = blockIdx.y * 16;
    const int bn = blockIdx.x * 128;

    const int lr = tid >> 3;            // 0..15
    const int lc = (tid & 7) * 4;       // 0..28

    float acc[4][4];
    #pragma unroll
    for (int j = 0; j < 4; j++)
        #pragma unroll
        for (int k = 0; k < 4; k++) acc[j][k] = 0.f;

    const int am = bm + lr;
    const bool aok = (am < M);
    const float* Arow = A + (size_t)(aok ? am : 0) * KDIM;

    const float* Brow[8];
    #pragma unroll
    for (int i = 0; i < 8; i++) {
        int n = bn + lr + 16 * i;
        Brow[i] = (n < nsplit) ? (B0 + (size_t)n * KDIM)
                               : (B1 + (size_t)(n - nsplit) * KDIM);
    }

    float4 pa;
    float4 pb[8];
    pa = aok ? *(const float4*)(Arow + lc) : make_float4(0.f, 0.f, 0.f, 0.f);
    #pragma unroll
    for (int i = 0; i < 8; i++) pb[i] = *(const float4*)(Brow[i] + lc);

    const int NK = KDIM / BK;
    for (int kt = 0; kt < NK; kt++) {
        {
            float4 va = pa;
            va.x = cvt_tf32(va.x); va.y = cvt_tf32(va.y);
            va.z = cvt_tf32(va.z); va.w = cvt_tf32(va.w);
            *(float4*)&sA[lr][lc] = va;
        }
        #pragma unroll
        for (int i = 0; i < 8; i++) {
            float4 vb = pb[i];
            vb.x = cvt_tf32(vb.x); vb.y = cvt_tf32(vb.y);
            vb.z = cvt_tf32(vb.z); vb.w = cvt_tf32(vb.w);
            *(float4*)&sB[lr + 16 * i][lc] = vb;
        }
        __syncthreads();

        if (kt + 1 < NK) {
            const int k0 = (kt + 1) * BK;
            pa = aok ? *(const float4*)(Arow + k0 + lc) : make_float4(0.f, 0.f, 0.f, 0.f);
            #pragma unroll
            for (int i = 0; i < 8; i++) pb[i] = *(const float4*)(Brow[i] + k0 + lc);
        }

        #pragma unroll
        for (int kk = 0; kk < 4; kk++) {
            const int k = kk * 8;
            uint32_t af[4];
            {
                int r0 = lane >> 2;
                int c0 = k + (lane & 3);
                af[0] = __float_as_uint(sA[r0][c0]);
                af[1] = __float_as_uint(sA[r0 + 8][c0]);
                af[2] = __float_as_uint(sA[r0][c0 + 4]);
                af[3] = __float_as_uint(sA[r0 + 8][c0 + 4]);
            }
            uint32_t bf[4][2];
            #pragma unroll
            for (int nf = 0; nf < 4; nf++) {
                int n0 = wn + nf * 8 + (lane >> 2);
                int kr = k + (lane & 3);
                bf[nf][0] = __float_as_uint(sB[n0][kr]);
                bf[nf][1] = __float_as_uint(sB[n0][kr + 4]);
            }
            #pragma unroll
            for (int nf = 0; nf < 4; nf++)
                mma_16x8x8(acc[nf], af, bf[nf]);
        }
        __syncthreads();
    }

    #pragma unroll
    for (int nf = 0; nf < 4; nf++) {
        int c0 = bn + wn + nf * 8 + (lane & 3) * 2;
        const float* bp = (c0 < nsplit) ? bias0 : bias1;
        int cb = (c0 < nsplit) ? c0 : c0 - nsplit;
        float bv0 = bp[cb], bv1 = bp[cb + 1];
        int r0 = bm + (lane >> 2);
        if (r0 < M) {
            C[(size_t)r0 * Ntot + c0]     = acc[nf][0] + bv0;
            C[(size_t)r0 * Ntot + c0 + 1] = acc[nf][1] + bv1;
        }
        if (r0 + 8 < M) {
            C[(size_t)(r0 + 8) * Ntot + c0]     = acc[nf][2] + bv0;
            C[(size_t)(r0 + 8) * Ntot + c0 + 1] = acc[nf][3] + bv1;
        }
    }
}

// ================= small-M tree GEMM (M <= 2) =============================
__global__ void __launch_bounds__(256)
smallM_gemm(const float* __restrict__ hrow,
            const float* __restrict__ Wl, const float* __restrict__ Wr,
            const float* __restrict__ bl, const float* __restrict__ br,
            float* __restrict__ gh, int M)
{
    const int w    = (blockIdx.x * blockDim.x + threadIdx.x) >> 5;   // 0..6143
    const int lane = threadIdx.x & 31;

    const float* Wrow;
    float bias;
    if (w < 3 * H) { Wrow = Wl + (size_t)w * KDIM;           bias = bl[w]; }
    else           { Wrow = Wr + (size_t)(w - 3 * H) * KDIM; bias = br[w - 3 * H]; }

    float4 wr[8];
    #pragma unroll
    for (int i = 0; i < 8; i++) wr[i] = ((const float4*)Wrow)[lane + 32 * i];

    for (int m = 0; m < M; m++) {
        const float4* h4 = (const float4*)(hrow + (size_t)m * KDIM);
        float s = 0.f;
        #pragma unroll
        for (int i = 0; i < 8; i++) {
            float4 hv = h4[lane + 32 * i];
            s += wr[i].x * hv.x + wr[i].y * hv.y + wr[i].z * hv.z + wr[i].w * hv.w;
        }
        #pragma unroll
        for (int o = 16; o; o >>= 1) s += __shfl_xor_sync(0xffffffffu, s, o);
        if (lane == 0) gh[(size_t)m * (6 * H) + w] = s + bias;
    }
}

// ================= fp16 GEMM (final logits) ===============================
// C[1024, V] = A[1024, 1024] @ B^T + bias.  M = 1024 exactly (no guards).
// 3-stage cp.async, BK=64; __launch_bounds__(256,2) targets 2 CTAs/SM
// (2 x 110.6 KB smem fits the 228 KB budget; regs capped at 128).
#define FBM 128
#define FBN 128
#define FBK 64
#define FSTRIDE 72                        // halves per smem row (64 + 8 pad)
#define FA_BYTES (FBM * FSTRIDE * 2)      // 18432
#define FSTAGE_BYTES (2 * FA_BYTES)       // 36864 (A tile + B tile)
#define FNKT (KDIM / FBK)                 // 16
#define FSMEM (3 * FSTAGE_BYTES)          // 110592

__device__ __forceinline__ void mma_f16m(float c[4], const uint32_t a[4], const uint32_t b[2]) {
    asm volatile(
        "mma.sync.aligned.m16n8k16.row.col.f32.f16.f16.f32 "
        "{%0,%1,%2,%3}, {%4,%5,%6,%7}, {%8,%9}, {%0,%1,%2,%3};\n"
        : "+f"(c[0]), "+f"(c[1]), "+f"(c[2]), "+f"(c[3])
        : "r"(a[0]), "r"(a[1]), "r"(a[2]), "r"(a[3]), "r"(b[0]), "r"(b[1]));
}

__device__ __forceinline__ void f16_load_stage(uint32_t sbase, int s, int kt,
        const __half* __restrict__ Ah, const __half* __restrict__ Bh,
        int bm, int bn, int tid)
{
    uint32_t st = sbase + s * FSTAGE_BYTES;
    const int kb = kt * FBK;
    #pragma unroll
    for (int i = 0; i < 4; i++) {
        int ch = tid + 256 * i;                 // 0..1023
        int row = ch >> 3, c8 = ch & 7;
        uint32_t d = st + row * (FSTRIDE * 2) + c8 * 16;
        cp16(d,            Ah + (size_t)(bm + row) * KDIM + kb + c8 * 8);
        cp16(d + FA_BYTES, Bh + (size_t)(bn + row) * KDIM + kb + c8 * 8);
    }
}

__global__ void __launch_bounds__(256, 2)
gemm_f16(const __half* __restrict__ Ah, const __half* __restrict__ Bh,
         const float* __restrict__ bias, float* __restrict__ C, int Ntot)
{
    extern __shared__ char smem[];
    const int tid  = threadIdx.x;
    const int lane = tid & 31;
    const int warp = tid >> 5;
    const int wm = (warp >> 2) * 64;
    const int wn = (warp & 3) * 32;
    const int bm = blockIdx.y * FBM;
    const int bn = blockIdx.x * FBN;
    const uint32_t sb = smem_u32(smem);

    float acc[4][4][4];
    #pragma unroll
    for (int i = 0; i < 4; i++)
        #pragma unroll
        for (int j = 0; j < 4; j++)
            #pragma unroll
            for (int k = 0; k < 4; k++) acc[i][j][k] = 0.f;

    f16_load_stage(sb, 0, 0, Ah, Bh, bm, bn, tid);
    asm volatile("cp.async.commit_group;" ::: "memory");
    f16_load_stage(sb, 1, 1, Ah, Bh, bm, bn, tid);
    asm volatile("cp.async.commit_group;" ::: "memory");

    for (int kt = 0; kt < FNKT; kt++) {
        if (kt < FNKT - 1) asm volatile("cp.async.wait_group 1;" ::: "memory");
        else               asm volatile("cp.async.wait_group 0;" ::: "memory");
        __syncthreads();

        if (kt + 2 < FNKT) {
            f16_load_stage(sb, (kt + 2) % 3, kt + 2, Ah, Bh, bm, bn, tid);
            asm volatile("cp.async.commit_group;" ::: "memory");
        }

        const __half* sA = (const __half*)(smem + (kt % 3) * FSTAGE_BYTES);
        const __half* sB = (const __half*)(smem + (kt % 3) * FSTAGE_BYTES + FA_BYTES);

        #pragma unroll
        for (int kc = 0; kc < 4; kc++) {
            const int k0 = kc * 16;
            uint32_t af[4][4], bf[4][2];
            #pragma unroll
            for (int mf = 0; mf < 4; mf++) {
                const __half* p = sA + (wm + mf * 16 + (lane >> 2)) * FSTRIDE
                                     + k0 + (lane & 3) * 2;
                af[mf][0] = *(const uint32_t*)p;
                af[mf][1] = *(const uint32_t*)(p + 8 * FSTRIDE);
                af[mf][2] = *(const uint32_t*)(p + 8);
                af[mf][3] = *(const uint32_t*)(p + 8 * FSTRIDE + 8);
            }
            #pragma unroll
            for (int nf = 0; nf < 4; nf++) {
                const __half* p = sB + (wn + nf * 8 + (lane >> 2)) * FSTRIDE
                                     + k0 + (lane & 3) * 2;
                bf[nf][0] = *(const uint32_t*)p;
                bf[nf][1] = *(const uint32_t*)(p + 8);
            }
            #pragma unroll
            for (int mf = 0; mf < 4; mf++)
                #pragma unroll
                for (int nf = 0; nf < 4; nf++)
                    mma_f16m(acc[mf][nf], af[mf], bf[nf]);
        }
    }

    // epilogue (+bias); M = 1024, all rows valid
    #pragma unroll
    for (int nf = 0; nf < 4; nf++) {
        int c0 = bn + wn + nf * 8 + (lane & 3) * 2;
        float bv0 = __ldg(bias + c0), bv1 = __ldg(bias + c0 + 1);
        #pragma unroll
        for (int mf = 0; mf < 4; mf++) {
            int r0 = bm + wm + mf * 16 + (lane >> 2);
            C[(size_t)r0 * Ntot + c0]           = acc[mf][nf][0] + bv0;
            C[(size_t)r0 * Ntot + c0 + 1]       = acc[mf][nf][1] + bv1;
            C[(size_t)(r0 + 8) * Ntot + c0]     = acc[mf][nf][2] + bv0;
            C[(size_t)(r0 + 8) * Ntot + c0 + 1] = acc[mf][nf][3] + bv1;
        }
    }
}

// ================= GRU gate fusion + interleave ===========================
__device__ __forceinline__ float sigmoidf_(float x) { return 1.f / (1.f + expf(-x)); }

__global__ void gru_gates(const float* __restrict__ hcur,
                          const float* __restrict__ bih_l,
                          const float* __restrict__ bih_r,
                          float* __restrict__ hnext, int M)
{
    int idx = blockIdx.x * blockDim.x + threadIdx.x;
    if (idx >= M * H) return;
    int n = idx >> 10;
    int j = idx & (H - 1);
    float h = hcur[idx];
    const float* gh = g_gh + (size_t)n * (6 * H);   // bhh already added by GEMM

    {   // left child -> row 2n
        float r  = sigmoidf_(bih_l[j]         + gh[j]);
        float z  = sigmoidf_(bih_l[H + j]     + gh[H + j]);
        float nn = tanhf   (bih_l[2 * H + j]  + r * gh[2 * H + j]);
        hnext[(size_t)(2 * n) * H + j] = (1.f - z) * nn + z * h;
    }
    {   // right child -> row 2n+1
        const float* ghr = gh + 3 * H;
        float r  = sigmoidf_(bih_r[j]         + ghr[j]);
        float z  = sigmoidf_(bih_r[H + j]     + ghr[H + j]);
        float nn = tanhf   (bih_r[2 * H + j]  + r * ghr[2 * H + j]);
        hnext[(size_t)(2 * n + 1) * H + j] = (1.f - z) * nn + z * h;
    }
}

// ================= row-wise log_softmax (smem-resident row, 512 thr) ======
__global__ void __launch_bounds__(512) log_softmax_rows(float* __restrict__ out)
{
    extern __shared__ float sx[];                  // V floats (128000 B)
    const int row = blockIdx.x;
    float* x = out + (size_t)row * V;
    float4* x4 = (float4*)x;
    float4* s4 = (float4*)sx;
    const int V4 = V / 4;                          // 8000
    __shared__ float redm[16];
    __shared__ float reds[16];
    const int tid = threadIdx.x, lane = tid & 31, warp = tid >> 5;

    float m = -1e30f;
    for (int i = tid; i < V4; i += 512) {
        float4 v = x4[i];
        s4[i] = v;
        m = fmaxf(m, fmaxf(fmaxf(v.x, v.y), fmaxf(v.z, v.w)));
    }
    #pragma unroll
    for (int o = 16; o; o >>= 1) m = fmaxf(m, __shfl_xor_sync(0xffffffffu, m, o));
    if (lane == 0) redm[warp] = m;
    __syncthreads();
    if (warp == 0) {
        m = (lane < 16) ? redm[lane] : -1e30f;
        #pragma unroll
        for (int o = 8; o; o >>= 1) m = fmaxf(m, __shfl_xor_sync(0xffffffffu, m, o));
        if (lane == 0) redm[0] = m;
    }
    __syncthreads();
    m = redm[0];

    float s = 0.f;
    for (int i = tid; i < V4; i += 512) {
        float4 v = s4[i];
        s += expf(v.x - m) + expf(v.y - m) + expf(v.z - m) + expf(v.w - m);
    }
    #pragma unroll
    for (int o = 16; o; o >>= 1) s += __shfl_xor_sync(0xffffffffu, s, o);
    if (lane == 0) reds[warp] = s;
    __syncthreads();
    if (warp == 0) {
        s = (lane < 16) ? reds[lane] : 0.f;
        #pragma unroll
        for (int o = 8; o; o >>= 1) s += __shfl_xor_sync(0xffffffffu, s, o);
        if (lane == 0) reds[0] = s;
    }
    __syncthreads();
    const float lse = m + logf(reds[0]);

    for (int i = tid; i < V4; i += 512) {
        float4 v = s4[i];
        v.x -= lse; v.y -= lse; v.z -= lse; v.w -= lse;
        x4[i] = v;
    }
}

// ================= launch =================================================
extern "C" void kernel_launch(void* const* d_in, const int* in_sizes, int n_in,
                              void* d_out, int out_size)
{
    const float* hidden = (const float*)d_in[0];
    const float* Whh_l  = (const float*)d_in[1];
    const float* bih_l  = (const float*)d_in[2];
    const float* bhh_l  = (const float*)d_in[3];
    const float* Whh_r  = (const float*)d_in[4];
    const float* bih_r  = (const float*)d_in[5];
    const float* bhh_r  = (const float*)d_in[6];
    const float* Wout   = (const float*)d_in[7];
    const float* bout   = (const float*)d_in[8];
    float* out = (float*)d_out;

    float *h0, *h1, *gh;
    __half *ahalf, *whalf;
    cudaGetSymbolAddress((void**)&h0,    g_h0);
    cudaGetSymbolAddress((void**)&h1,    g_h1);
    cudaGetSymbolAddress((void**)&gh,    g_gh);
    cudaGetSymbolAddress((void**)&ahalf, g_ahalf);
    cudaGetSymbolAddress((void**)&whalf, g_whalf);

    cudaFuncSetAttribute(gemm_f16, cudaFuncAttributeMaxDynamicSharedMemorySize, FSMEM);
    cudaFuncSetAttribute(log_softmax_rows, cudaFuncAttributeMaxDynamicSharedMemorySize,
                         V * (int)sizeof(float));

    // Wout -> fp16 (every call; deterministic)
    const int nW4 = V * H / 4;
    conv_f16<<<(nW4 + 255) / 256, 256>>>(Wout, whalf, nW4);

    cudaMemcpyAsync(h0, hidden, H * sizeof(float), cudaMemcpyDeviceToDevice);

    float* cur = h0;
    float* nxt = h1;
    for (int d = 0; d < DEPTH; d++) {
        const int M = 1 << d;
        if (M <= 2) {
            smallM_gemm<<<6 * H / 8, 256>>>(cur, Whh_l, Whh_r, bhh_l, bhh_r, gh, M);
        } else if (M <= 64) {
            dim3 grid(6 * H / 128, (M + 15) / 16);
            gemm_tf32_m16<<<grid, 128>>>(cur, M, Whh_l, Whh_r, 3 * H,
                                         bhh_l, bhh_r, gh, 6 * H);
        } else {
            dim3 grid(6 * H / BN, (M + BM - 1) / BM);
            gemm_tf32<<<grid, 256>>>(cur, M, Whh_l, Whh_r, 3 * H,
                                     bhh_l, bhh_r, gh, 6 * H);
        }
        gru_gates<<<(M * H + 255) / 256, 256>>>(cur, bih_l, bih_r, nxt, M);
        float* t = cur; cur = nxt; nxt = t;
    }

    // final: logits = h @ Wout^T + bout (fp16 tensor-core GEMM into d_out)
    const int nA4 = 1024 * H / 4;
    conv_f16<<<(nA4 + 255) / 256, 256>>>(cur, ahalf, nA4);
    dim3 gridf(V / FBN, 1024 / FBM);                 // (250, 8)
    gemm_f16<<<gridf, 256, FSMEM>>>(ahalf, whalf, bout, out, V);

    log_softmax_rows<<<1024, 512, V * sizeof(float)>>>(out);
}

// round 17
// speedup vs baseline: 1.4523x; 1.0644x over previous
#include <cuda_runtime.h>
#include <cuda_fp16.h>
#include <cstdint>

#define H     1024
#define V     32000
#define DEPTH 10
#define KDIM  1024

// ---------------- scratch (no runtime allocation allowed) ----------------
__device__ float  g_h0[1024 * H];            // ping
__device__ float  g_h1[1024 * H];            // pong
__device__ float  g_gh[512 * 6 * H];         // gate pre-activations
__device__ __half g_ahalf[1024 * H];         // h in fp16 (final GEMM A)
__device__ __half g_whalf[(size_t)V * H];    // Wout in fp16 (final GEMM B)

// ---------------- common helpers -----------------------------------------
__device__ __forceinline__ uint32_t smem_u32(const void* p) {
    uint32_t a;
    asm("{ .reg .u64 t; cvta.to.shared.u64 t, %1; cvt.u32.u64 %0, t; }"
        : "=r"(a) : "l"(p));
    return a;
}
__device__ __forceinline__ void cp16(uint32_t dst, const void* src) {
    asm volatile("cp.async.cg.shared.global [%0], [%1], 16;" :: "r"(dst), "l"(src));
}
__device__ __forceinline__ void ldsm_x4(uint32_t r[4], uint32_t addr) {
    asm volatile("ldmatrix.sync.aligned.m8n8.x4.shared.b16 {%0,%1,%2,%3}, [%4];"
        : "=r"(r[0]), "=r"(r[1]), "=r"(r[2]), "=r"(r[3]) : "r"(addr));
}

// ================= fp32 -> fp16 conversion ================================
__global__ void conv_f16(const float* __restrict__ src, __half* __restrict__ dst, int n4)
{
    int i = blockIdx.x * blockDim.x + threadIdx.x;
    if (i >= n4) return;
    float4 v = ((const float4*)src)[i];
    __half2 a = __floats2half2_rn(v.x, v.y);
    __half2 b = __floats2half2_rn(v.z, v.w);
    uint2 p;
    p.x = *(uint32_t*)&a;
    p.y = *(uint32_t*)&b;
    ((uint2*)dst)[i] = p;
}

// ================= tf32 mma primitives ====================================
__device__ __forceinline__ float cvt_tf32(float x) {
    uint32_t b;
    asm("cvt.rna.tf32.f32 %0, %1;" : "=r"(b) : "f"(x));
    return __uint_as_float(b);
}

__device__ __forceinline__ void mma_16x8x8(float c[4], const uint32_t a[4], const uint32_t b[2]) {
    asm volatile(
        "mma.sync.aligned.m16n8k8.row.col.f32.tf32.tf32.f32 "
        "{%0,%1,%2,%3}, {%4,%5,%6,%7}, {%8,%9}, {%0,%1,%2,%3};\n"
        : "+f"(c[0]), "+f"(c[1]), "+f"(c[2]), "+f"(c[3])
        : "r"(a[0]), "r"(a[1]), "r"(a[2]), "r"(a[3]), "r"(b[0]), "r"(b[1]));
}

#define BK 32
#define PAD 4

// ================= tf32 GEMM, BM=64 tile (tree levels M>=128) =============
// 256 threads = 8 warps (2 x 4); CTA tile 64 x 128; warp tile 32 x 32.
__global__ void __launch_bounds__(256, 2)
gemm_tf32_m64(const float* __restrict__ A, int M,
              const float* __restrict__ B0, const float* __restrict__ B1, int nsplit,
              const float* __restrict__ bias0, const float* __restrict__ bias1,
              float* __restrict__ C, int Ntot)
{
    __shared__ float sA[64][BK + PAD];
    __shared__ float sB[128][BK + PAD];

    const int tid  = threadIdx.x;
    const int lane = tid & 31;
    const int warp = tid >> 5;
    const int wm = (warp >> 2) * 32;     // 0 or 32
    const int wn = (warp & 3) * 32;
    const int bm = blockIdx.y * 64;      // M multiple of 64 -> no row guards
    const int bn = blockIdx.x * 128;

    const int lr = tid >> 3;             // 0..31
    const int lc = (tid & 7) * 4;

    float acc[2][4][4];
    #pragma unroll
    for (int i = 0; i < 2; i++)
        #pragma unroll
        for (int j = 0; j < 4; j++)
            #pragma unroll
            for (int k = 0; k < 4; k++) acc[i][j][k] = 0.f;

    const float* Arow[2];
    const float* Brow[4];
    #pragma unroll
    for (int i = 0; i < 2; i++)
        Arow[i] = A + (size_t)(bm + lr + 32 * i) * KDIM;
    #pragma unroll
    for (int i = 0; i < 4; i++) {
        int n = bn + lr + 32 * i;
        Brow[i] = (n < nsplit) ? (B0 + (size_t)n * KDIM)
                               : (B1 + (size_t)(n - nsplit) * KDIM);
    }

    float4 pa[2], pb[4];
    #pragma unroll
    for (int i = 0; i < 2; i++) pa[i] = *(const float4*)(Arow[i] + lc);
    #pragma unroll
    for (int i = 0; i < 4; i++) pb[i] = *(const float4*)(Brow[i] + lc);

    const int NK = KDIM / BK;
    for (int kt = 0; kt < NK; kt++) {
        #pragma unroll
        for (int i = 0; i < 2; i++) {
            float4 va = pa[i];
            va.x = cvt_tf32(va.x); va.y = cvt_tf32(va.y);
            va.z = cvt_tf32(va.z); va.w = cvt_tf32(va.w);
            *(float4*)&sA[lr + 32 * i][lc] = va;
        }
        #pragma unroll
        for (int i = 0; i < 4; i++) {
            float4 vb = pb[i];
            vb.x = cvt_tf32(vb.x); vb.y = cvt_tf32(vb.y);
            vb.z = cvt_tf32(vb.z); vb.w = cvt_tf32(vb.w);
            *(float4*)&sB[lr + 32 * i][lc] = vb;
        }
        __syncthreads();

        if (kt + 1 < NK) {
            const int k0 = (kt + 1) * BK;
            #pragma unroll
            for (int i = 0; i < 2; i++) pa[i] = *(const float4*)(Arow[i] + k0 + lc);
            #pragma unroll
            for (int i = 0; i < 4; i++) pb[i] = *(const float4*)(Brow[i] + k0 + lc);
        }

        #pragma unroll
        for (int kk = 0; kk < 4; kk++) {
            const int k = kk * 8;
            uint32_t af[2][4];
            #pragma unroll
            for (int mf = 0; mf < 2; mf++) {
                int r0 = wm + mf * 16 + (lane >> 2);
                int c0 = k + (lane & 3);
                af[mf][0] = __float_as_uint(sA[r0][c0]);
                af[mf][1] = __float_as_uint(sA[r0 + 8][c0]);
                af[mf][2] = __float_as_uint(sA[r0][c0 + 4]);
                af[mf][3] = __float_as_uint(sA[r0 + 8][c0 + 4]);
            }
            uint32_t bf[4][2];
            #pragma unroll
            for (int nf = 0; nf < 4; nf++) {
                int n0 = wn + nf * 8 + (lane >> 2);
                int kr = k + (lane & 3);
                bf[nf][0] = __float_as_uint(sB[n0][kr]);
                bf[nf][1] = __float_as_uint(sB[n0][kr + 4]);
            }
            #pragma unroll
            for (int mf = 0; mf < 2; mf++)
                #pragma unroll
                for (int nf = 0; nf < 4; nf++)
                    mma_16x8x8(acc[mf][nf], af[mf], bf[nf]);
        }
        __syncthreads();
    }

    #pragma unroll
    for (int nf = 0; nf < 4; nf++) {
        int c0 = bn + wn + nf * 8 + (lane & 3) * 2;
        const float* bp = (c0 < nsplit) ? bias0 : bias1;
        int cb = (c0 < nsplit) ? c0 : c0 - nsplit;
        float bv0 = bp[cb], bv1 = bp[cb + 1];
        #pragma unroll
        for (int mf = 0; mf < 2; mf++) {
            int r0 = bm + wm + mf * 16 + (lane >> 2);
            C[(size_t)r0 * Ntot + c0]           = acc[mf][nf][0] + bv0;
            C[(size_t)r0 * Ntot + c0 + 1]       = acc[mf][nf][1] + bv1;
            C[(size_t)(r0 + 8) * Ntot + c0]     = acc[mf][nf][2] + bv0;
            C[(size_t)(r0 + 8) * Ntot + c0 + 1] = acc[mf][nf][3] + bv1;
        }
    }
}

// ================= tf32 GEMM, BM=16 tile (tree levels M=4..64) ============
// 128 threads = 4 warps; CTA tile 16 x 128; warp tile 16 x 32.
__global__ void __launch_bounds__(128, 1)
gemm_tf32_m16(const float* __restrict__ A, int M,
              const float* __restrict__ B0, const float* __restrict__ B1, int nsplit,
              const float* __restrict__ bias0, const float* __restrict__ bias1,
              float* __restrict__ C, int Ntot)
{
    __shared__ float sA[16][BK + PAD];
    __shared__ float sB[128][BK + PAD];

    const int tid  = threadIdx.x;
    const int lane = tid & 31;
    const int warp = tid >> 5;          // 0..3
    const int wn   = warp * 32;
    const int bm = blockIdx.y * 16;
    const int bn = blockIdx.x * 128;

    const int lr = tid >> 3;            // 0..15
    const int lc = (tid & 7) * 4;       // 0..28

    float acc[4][4];
    #pragma unroll
    for (int j = 0; j < 4; j++)
        #pragma unroll
        for (int k = 0; k < 4; k++) acc[j][k] = 0.f;

    const int am = bm + lr;
    const bool aok = (am < M);
    const float* Arow = A + (size_t)(aok ? am : 0) * KDIM;

    const float* Brow[8];
    #pragma unroll
    for (int i = 0; i < 8; i++) {
        int n = bn + lr + 16 * i;
        Brow[i] = (n < nsplit) ? (B0 + (size_t)n * KDIM)
                               : (B1 + (size_t)(n - nsplit) * KDIM);
    }

    float4 pa;
    float4 pb[8];
    pa = aok ? *(const float4*)(Arow + lc) : make_float4(0.f, 0.f, 0.f, 0.f);
    #pragma unroll
    for (int i = 0; i < 8; i++) pb[i] = *(const float4*)(Brow[i] + lc);

    const int NK = KDIM / BK;
    for (int kt = 0; kt < NK; kt++) {
        {
            float4 va = pa;
            va.x = cvt_tf32(va.x); va.y = cvt_tf32(va.y);
            va.z = cvt_tf32(va.z); va.w = cvt_tf32(va.w);
            *(float4*)&sA[lr][lc] = va;
        }
        #pragma unroll
        for (int i = 0; i < 8; i++) {
            float4 vb = pb[i];
            vb.x = cvt_tf32(vb.x); vb.y = cvt_tf32(vb.y);
            vb.z = cvt_tf32(vb.z); vb.w = cvt_tf32(vb.w);
            *(float4*)&sB[lr + 16 * i][lc] = vb;
        }
        __syncthreads();

        if (kt + 1 < NK) {
            const int k0 = (kt + 1) * BK;
            pa = aok ? *(const float4*)(Arow + k0 + lc) : make_float4(0.f, 0.f, 0.f, 0.f);
            #pragma unroll
            for (int i = 0; i < 8; i++) pb[i] = *(const float4*)(Brow[i] + k0 + lc);
        }

        #pragma unroll
        for (int kk = 0; kk < 4; kk++) {
            const int k = kk * 8;
            uint32_t af[4];
            {
                int r0 = lane >> 2;
                int c0 = k + (lane & 3);
                af[0] = __float_as_uint(sA[r0][c0]);
                af[1] = __float_as_uint(sA[r0 + 8][c0]);
                af[2] = __float_as_uint(sA[r0][c0 + 4]);
                af[3] = __float_as_uint(sA[r0 + 8][c0 + 4]);
            }
            uint32_t bf[4][2];
            #pragma unroll
            for (int nf = 0; nf < 4; nf++) {
                int n0 = wn + nf * 8 + (lane >> 2);
                int kr = k + (lane & 3);
                bf[nf][0] = __float_as_uint(sB[n0][kr]);
                bf[nf][1] = __float_as_uint(sB[n0][kr + 4]);
            }
            #pragma unroll
            for (int nf = 0; nf < 4; nf++)
                mma_16x8x8(acc[nf], af, bf[nf]);
        }
        __syncthreads();
    }

    #pragma unroll
    for (int nf = 0; nf < 4; nf++) {
        int c0 = bn + wn + nf * 8 + (lane & 3) * 2;
        const float* bp = (c0 < nsplit) ? bias0 : bias1;
        int cb = (c0 < nsplit) ? c0 : c0 - nsplit;
        float bv0 = bp[cb], bv1 = bp[cb + 1];
        int r0 = bm + (lane >> 2);
        if (r0 < M) {
            C[(size_t)r0 * Ntot + c0]     = acc[nf][0] + bv0;
            C[(size_t)r0 * Ntot + c0 + 1] = acc[nf][1] + bv1;
        }
        if (r0 + 8 < M) {
            C[(size_t)(r0 + 8) * Ntot + c0]     = acc[nf][2] + bv0;
            C[(size_t)(r0 + 8) * Ntot + c0 + 1] = acc[nf][3] + bv1;
        }
    }
}

// ================= small-M tree GEMM (M <= 2) =============================
__global__ void __launch_bounds__(256)
smallM_gemm(const float* __restrict__ hrow,
            const float* __restrict__ Wl, const float* __restrict__ Wr,
            const float* __restrict__ bl, const float* __restrict__ br,
            float* __restrict__ gh, int M)
{
    const int w    = (blockIdx.x * blockDim.x + threadIdx.x) >> 5;   // 0..6143
    const int lane = threadIdx.x & 31;

    const float* Wrow;
    float bias;
    if (w < 3 * H) { Wrow = Wl + (size_t)w * KDIM;           bias = bl[w]; }
    else           { Wrow = Wr + (size_t)(w - 3 * H) * KDIM; bias = br[w - 3 * H]; }

    float4 wr[8];
    #pragma unroll
    for (int i = 0; i < 8; i++) wr[i] = ((const float4*)Wrow)[lane + 32 * i];

    for (int m = 0; m < M; m++) {
        const float4* h4 = (const float4*)(hrow + (size_t)m * KDIM);
        float s = 0.f;
        #pragma unroll
        for (int i = 0; i < 8; i++) {
            float4 hv = h4[lane + 32 * i];
            s += wr[i].x * hv.x + wr[i].y * hv.y + wr[i].z * hv.z + wr[i].w * hv.w;
        }
        #pragma unroll
        for (int o = 16; o; o >>= 1) s += __shfl_xor_sync(0xffffffffu, s, o);
        if (lane == 0) gh[(size_t)m * (6 * H) + w] = s + bias;
    }
}

// ================= fp16 GEMM (final logits), ldmatrix fragments ===========
// C[1024, V] = A[1024, 1024] @ B^T + bias.  M = 1024 exactly (no guards).
// 3-stage cp.async, BK=64; 2 CTAs/SM; ldmatrix.x4 fragment loads.
#define FBM 128
#define FBN 128
#define FBK 64
#define FSTRIDE 72                        // halves per smem row (64 + 8 pad) = 144 B (16B-mult)
#define FA_BYTES (FBM * FSTRIDE * 2)      // 18432
#define FSTAGE_BYTES (2 * FA_BYTES)       // 36864 (A tile + B tile)
#define FNKT (KDIM / FBK)                 // 16
#define FSMEM (3 * FSTAGE_BYTES)          // 110592

__device__ __forceinline__ void mma_f16m(float c[4], const uint32_t a[4], const uint32_t b[2]) {
    asm volatile(
        "mma.sync.aligned.m16n8k16.row.col.f32.f16.f16.f32 "
        "{%0,%1,%2,%3}, {%4,%5,%6,%7}, {%8,%9}, {%0,%1,%2,%3};\n"
        : "+f"(c[0]), "+f"(c[1]), "+f"(c[2]), "+f"(c[3])
        : "r"(a[0]), "r"(a[1]), "r"(a[2]), "r"(a[3]), "r"(b[0]), "r"(b[1]));
}

__device__ __forceinline__ void f16_load_stage(uint32_t sbase, int s, int kt,
        const __half* __restrict__ Ah, const __half* __restrict__ Bh,
        int bm, int bn, int tid)
{
    uint32_t st = sbase + s * FSTAGE_BYTES;
    const int kb = kt * FBK;
    #pragma unroll
    for (int i = 0; i < 4; i++) {
        int ch = tid + 256 * i;                 // 0..1023
        int row = ch >> 3, c8 = ch & 7;
        uint32_t d = st + row * (FSTRIDE * 2) + c8 * 16;
        cp16(d,            Ah + (size_t)(bm + row) * KDIM + kb + c8 * 8);
        cp16(d + FA_BYTES, Bh + (size_t)(bn + row) * KDIM + kb + c8 * 8);
    }
}

__global__ void __launch_bounds__(256, 2)
gemm_f16(const __half* __restrict__ Ah, const __half* __restrict__ Bh,
         const float* __restrict__ bias, float* __restrict__ C, int Ntot)
{
    extern __shared__ char smem[];
    const int tid  = threadIdx.x;
    const int lane = tid & 31;
    const int warp = tid >> 5;
    const int wm = (warp >> 2) * 64;
    const int wn = (warp & 3) * 32;
    const int bm = blockIdx.y * FBM;
    const int bn = blockIdx.x * FBN;
    const uint32_t sb = smem_u32(smem);

    // ldmatrix lane->row/k mapping (reproduces the scalar af/bf layouts)
    const int arow = (lane & 7) + ((lane >> 3) & 1) * 8;   // A: m0 r0-7/k0, m1 r8-15/k0, m2 r0-7/k8, m3 r8-15/k8
    const int akof = (lane >> 4) * 8;
    const int brow = (lane & 7) + (lane >> 4) * 8;          // B: m0 n0-7/k0, m1 n0-7/k8, m2 n8-15/k0, m3 n8-15/k8
    const int bkof = ((lane >> 3) & 1) * 8;

    float acc[4][4][4];
    #pragma unroll
    for (int i = 0; i < 4; i++)
        #pragma unroll
        for (int j = 0; j < 4; j++)
            #pragma unroll
            for (int k = 0; k < 4; k++) acc[i][j][k] = 0.f;

    f16_load_stage(sb, 0, 0, Ah, Bh, bm, bn, tid);
    asm volatile("cp.async.commit_group;" ::: "memory");
    f16_load_stage(sb, 1, 1, Ah, Bh, bm, bn, tid);
    asm volatile("cp.async.commit_group;" ::: "memory");

    for (int kt = 0; kt < FNKT; kt++) {
        if (kt < FNKT - 1) asm volatile("cp.async.wait_group 1;" ::: "memory");
        else               asm volatile("cp.async.wait_group 0;" ::: "memory");
        __syncthreads();

        if (kt + 2 < FNKT) {
            f16_load_stage(sb, (kt + 2) % 3, kt + 2, Ah, Bh, bm, bn, tid);
            asm volatile("cp.async.commit_group;" ::: "memory");
        }

        const uint32_t a_base = sb + (kt % 3) * FSTAGE_BYTES;
        const uint32_t b_base = a_base + FA_BYTES;

        #pragma unroll
        for (int kc = 0; kc < 4; kc++) {
            const int k0 = kc * 16;
            uint32_t af[4][4], bf[4][2];
            #pragma unroll
            for (int mf = 0; mf < 4; mf++) {
                uint32_t addr = a_base +
                    ((wm + mf * 16 + arow) * FSTRIDE + k0 + akof) * 2;
                ldsm_x4(af[mf], addr);
            }
            #pragma unroll
            for (int nf2 = 0; nf2 < 2; nf2++) {
                uint32_t bq[4];
                uint32_t addr = b_base +
                    ((wn + nf2 * 16 + brow) * FSTRIDE + k0 + bkof) * 2;
                ldsm_x4(bq, addr);
                bf[2 * nf2][0]     = bq[0];
                bf[2 * nf2][1]     = bq[1];
                bf[2 * nf2 + 1][0] = bq[2];
                bf[2 * nf2 + 1][1] = bq[3];
            }
            #pragma unroll
            for (int mf = 0; mf < 4; mf++)
                #pragma unroll
                for (int nf = 0; nf < 4; nf++)
                    mma_f16m(acc[mf][nf], af[mf], bf[nf]);
        }
    }

    // epilogue (+bias); M = 1024, all rows valid
    #pragma unroll
    for (int nf = 0; nf < 4; nf++) {
        int c0 = bn + wn + nf * 8 + (lane & 3) * 2;
        float bv0 = __ldg(bias + c0), bv1 = __ldg(bias + c0 + 1);
        #pragma unroll
        for (int mf = 0; mf < 4; mf++) {
            int r0 = bm + wm + mf * 16 + (lane >> 2);
            C[(size_t)r0 * Ntot + c0]           = acc[mf][nf][0] + bv0;
            C[(size_t)r0 * Ntot + c0 + 1]       = acc[mf][nf][1] + bv1;
            C[(size_t)(r0 + 8) * Ntot + c0]     = acc[mf][nf][2] + bv0;
            C[(size_t)(r0 + 8) * Ntot + c0 + 1] = acc[mf][nf][3] + bv1;
        }
    }
}

// ================= GRU gate fusion + interleave ===========================
__device__ __forceinline__ float sigmoidf_(float x) { return 1.f / (1.f + expf(-x)); }

__global__ void gru_gates(const float* __restrict__ hcur,
                          const float* __restrict__ bih_l,
                          const float* __restrict__ bih_r,
                          float* __restrict__ hnext, int M)
{
    int idx = blockIdx.x * blockDim.x + threadIdx.x;
    if (idx >= M * H) return;
    int n = idx >> 10;
    int j = idx & (H - 1);
    float h = hcur[idx];
    const float* gh = g_gh + (size_t)n * (6 * H);   // bhh already added by GEMM

    {   // left child -> row 2n
        float r  = sigmoidf_(bih_l[j]         + gh[j]);
        float z  = sigmoidf_(bih_l[H + j]     + gh[H + j]);
        float nn = tanhf   (bih_l[2 * H + j]  + r * gh[2 * H + j]);
        hnext[(size_t)(2 * n) * H + j] = (1.f - z) * nn + z * h;
    }
    {   // right child -> row 2n+1
        const float* ghr = gh + 3 * H;
        float r  = sigmoidf_(bih_r[j]         + ghr[j]);
        float z  = sigmoidf_(bih_r[H + j]     + ghr[H + j]);
        float nn = tanhf   (bih_r[2 * H + j]  + r * ghr[2 * H + j]);
        hnext[(size_t)(2 * n + 1) * H + j] = (1.f - z) * nn + z * h;
    }
}

// ================= row-wise log_softmax (smem-resident row, 512 thr) ======
__global__ void __launch_bounds__(512) log_softmax_rows(float* __restrict__ out)
{
    extern __shared__ float sx[];                  // V floats (128000 B)
    const int row = blockIdx.x;
    float* x = out + (size_t)row * V;
    float4* x4 = (float4*)x;
    float4* s4 = (float4*)sx;
    const int V4 = V / 4;                          // 8000
    __shared__ float redm[16];
    __shared__ float reds[16];
    const int tid = threadIdx.x, lane = tid & 31, warp = tid >> 5;

    float m = -1e30f;
    for (int i = tid; i < V4; i += 512) {
        float4 v = x4[i];
        s4[i] = v;
        m = fmaxf(m, fmaxf(fmaxf(v.x, v.y), fmaxf(v.z, v.w)));
    }
    #pragma unroll
    for (int o = 16; o; o >>= 1) m = fmaxf(m, __shfl_xor_sync(0xffffffffu, m, o));
    if (lane == 0) redm[warp] = m;
    __syncthreads();
    if (warp == 0) {
        m = (lane < 16) ? redm[lane] : -1e30f;
        #pragma unroll
        for (int o = 8; o; o >>= 1) m = fmaxf(m, __shfl_xor_sync(0xffffffffu, m, o));
        if (lane == 0) redm[0] = m;
    }
    __syncthreads();
    m = redm[0];

    float s = 0.f;
    for (int i = tid; i < V4; i += 512) {
        float4 v = s4[i];
        s += expf(v.x - m) + expf(v.y - m) + expf(v.z - m) + expf(v.w - m);
    }
    #pragma unroll
    for (int o = 16; o; o >>= 1) s += __shfl_xor_sync(0xffffffffu, s, o);
    if (lane == 0) reds[warp] = s;
    __syncthreads();
    if (warp == 0) {
        s = (lane < 16) ? reds[lane] : 0.f;
        #pragma unroll
        for (int o = 8; o; o >>= 1) s += __shfl_xor_sync(0xffffffffu, s, o);
        if (lane == 0) reds[0] = s;
    }
    __syncthreads();
    const float lse = m + logf(reds[0]);

    for (int i = tid; i < V4; i += 512) {
        float4 v = s4[i];
        v.x -= lse; v.y -= lse; v.z -= lse; v.w -= lse;
        x4[i] = v;
    }
}

// ================= launch =================================================
extern "C" void kernel_launch(void* const* d_in, const int* in_sizes, int n_in,
                              void* d_out, int out_size)
{
    const float* hidden = (const float*)d_in[0];
    const float* Whh_l  = (const float*)d_in[1];
    const float* bih_l  = (const float*)d_in[2];
    const float* bhh_l  = (const float*)d_in[3];
    const float* Whh_r  = (const float*)d_in[4];
    const float* bih_r  = (const float*)d_in[5];
    const float* bhh_r  = (const float*)d_in[6];
    const float* Wout   = (const float*)d_in[7];
    const float* bout   = (const float*)d_in[8];
    float* out = (float*)d_out;

    float *h0, *h1, *gh;
    __half *ahalf, *whalf;
    cudaGetSymbolAddress((void**)&h0,    g_h0);
    cudaGetSymbolAddress((void**)&h1,    g_h1);
    cudaGetSymbolAddress((void**)&gh,    g_gh);
    cudaGetSymbolAddress((void**)&ahalf, g_ahalf);
    cudaGetSymbolAddress((void**)&whalf, g_whalf);

    cudaFuncSetAttribute(gemm_f16, cudaFuncAttributeMaxDynamicSharedMemorySize, FSMEM);
    cudaFuncSetAttribute(log_softmax_rows, cudaFuncAttributeMaxDynamicSharedMemorySize,
                         V * (int)sizeof(float));

    // Wout -> fp16 (every call; deterministic)
    const int nW4 = V * H / 4;
    conv_f16<<<(nW4 + 255) / 256, 256>>>(Wout, whalf, nW4);

    cudaMemcpyAsync(h0, hidden, H * sizeof(float), cudaMemcpyDeviceToDevice);

    float* cur = h0;
    float* nxt = h1;
    for (int d = 0; d < DEPTH; d++) {
        const int M = 1 << d;
        if (M <= 2) {
            smallM_gemm<<<6 * H / 8, 256>>>(cur, Whh_l, Whh_r, bhh_l, bhh_r, gh, M);
        } else if (M <= 64) {
            dim3 grid(6 * H / 128, (M + 15) / 16);
            gemm_tf32_m16<<<grid, 128>>>(cur, M, Whh_l, Whh_r, 3 * H,
                                         bhh_l, bhh_r, gh, 6 * H);
        } else {
            dim3 grid(6 * H / 128, M / 64);
            gemm_tf32_m64<<<grid, 256>>>(cur, M, Whh_l, Whh_r, 3 * H,
                                         bhh_l, bhh_r, gh, 6 * H);
        }
        gru_gates<<<(M * H + 255) / 256, 256>>>(cur, bih_l, bih_r, nxt, M);
        float* t = cur; cur = nxt; nxt = t;
    }

    // final: logits = h @ Wout^T + bout (fp16 tensor-core GEMM into d_out)
    const int nA4 = 1024 * H / 4;
    conv_f16<<<(nA4 + 255) / 256, 256>>>(cur, ahalf, nA4);
    dim3 gridf(V / FBN, 1024 / FBM);                 // (250, 8)
    gemm_f16<<<gridf, 256, FSMEM>>>(ahalf, whalf, bout, out, V);

    log_softmax_rows<<<1024, 512, V * sizeof(float)>>>(out);
}